// round 4
// baseline (speedup 1.0000x reference)
#include <cuda_runtime.h>
#include <cuda_fp16.h>
#include <cstdint>

// ============================================================================
// NCMOpenMax: probas = softmax(cos(X, muK), axis=1)
//   X [262144,128] f32, muK [512,128] f32, out [262144,512] f32
//
// fp16 mma.sync.m16n8k16; persistent clusters of 2 CTAs.
// Each cluster owns a 64-row tile; CTA rank r computes classes [256r,256r+256)
// with its half of B resident in smem (64 KB). Row-softmax denominators are
// exchanged via DSMEM (mapa + st.shared::cluster) around a split cluster
// barrier. cos<=1 => fixed-shift exp(s-1): exact softmax, no max pass.
// ============================================================================

static constexpr int DDIM = 128;
static constexpr int KCLS = 512;
static constexpr int BM   = 64;

// B fragments fp16, [rank(2)][s(8)][t(32)][lane(32)] x uint2 (4 halves)
__device__ __half g_bfrag[2 * 8 * 32 * 32 * 4];   // 128 KB

// ---- smem layout (bytes) ----
static constexpr int SM_B     = 0;                   // 65536
static constexpr int A_STRIDE = 272;                 // 136 halves/row (pad 8)
static constexpr int A_BYTES  = BM * A_STRIDE;       // 17408
static constexpr int SM_A0    = 65536;
static constexpr int SM_A1    = SM_A0 + A_BYTES;     // 82944
static constexpr int SM_NRM   = SM_A1 + A_BYTES;     // 100352 (2 x 64 f32)
static constexpr int SM_RS    = SM_NRM + 512;        // 100864 (8 x 64 f32)
static constexpr int SM_INV   = SM_RS + 2048;        // 102912 (64 f32)
static constexpr int SM_PEER  = SM_INV + 256;        // 103168 (2 x 64 f32)
static constexpr int SM_TOTAL = SM_PEER + 512;       // 103680

__device__ __forceinline__ uint32_t smem_u32(const void* p) {
    uint32_t a;
    asm("{ .reg .u64 t; cvta.to.shared.u64 t, %1; cvt.u32.u64 %0, t; }"
        : "=r"(a) : "l"(p));
    return a;
}

#define CP_ASYNC16(dst_u32, src_ptr) \
    asm volatile("cp.async.cg.shared.global [%0], [%1], 16;" \
                 :: "r"(dst_u32), "l"(src_ptr) : "memory")

__device__ __forceinline__ void mma_f16(float* d, const uint32_t* a,
                                        uint32_t b0, uint32_t b1) {
    asm volatile(
        "mma.sync.aligned.m16n8k16.row.col.f32.f16.f16.f32 "
        "{%0,%1,%2,%3},{%4,%5,%6,%7},{%8,%9},{%0,%1,%2,%3};"
        : "+f"(d[0]), "+f"(d[1]), "+f"(d[2]), "+f"(d[3])
        : "r"(a[0]), "r"(a[1]), "r"(a[2]), "r"(a[3]), "r"(b0), "r"(b1));
}

// ---------------- prep: normalize muK -> fp16 fragment order ----------------

__global__ void ncm_prep(const float* __restrict__ muK) {
    __shared__ float pp[4];
    int n = blockIdx.x;       // class
    int k = threadIdx.x;      // feature
    float v = muK[n * DDIM + k];
    float ss = v * v;
    #pragma unroll
    for (int o = 16; o > 0; o >>= 1)
        ss += __shfl_xor_sync(0xffffffffu, ss, o);
    if ((k & 31) == 0) pp[k >> 5] = ss;
    __syncthreads();
    float inv = 1.0f / fmaxf(sqrtf(pp[0] + pp[1] + pp[2] + pp[3]), 1e-8f);

    // m16n8k16 .col B fragment mapping
    int s    = k >> 4;
    int kk   = k & 15;
    int rk   = n >> 8;              // which CTA half
    int t    = (n >> 3) & 31;       // local 8-class tile
    int lane = (n & 7) * 4 + ((kk & 7) >> 1);
    int idx  = ((kk >= 8) ? 2 : 0) + (kk & 1);
    g_bfrag[((((rk * 8 + s) * 32 + t) * 32 + lane) << 2) + idx] =
        __float2half_rn(v * inv);
}

// ---------------- main ----------------

__global__ void __launch_bounds__(256, 2) __cluster_dims__(2, 1, 1)
ncm_main(const float* __restrict__ X, float* __restrict__ out,
         int tiles, int nclusters) {
    extern __shared__ char smem[];
    const uint32_t sb = smem_u32(smem);
    const int tid  = threadIdx.x;
    const int lane = tid & 31;
    const int wid  = tid >> 5;
    const int g    = lane >> 2;
    const int kq   = lane & 3;

    uint32_t rank;
    asm("mov.u32 %0, %%cluster_ctarank;" : "=r"(rank));
    const int cid = blockIdx.x >> 1;

    // ldmatrix lane addressing
    const int m_    = lane >> 3;
    const int lrow  = ((m_ & 1) << 3) + (lane & 7);
    const int lkoff = (m_ >> 1) << 4;

    // ---- load this CTA's B half (64 KB) once ----
    {
        const char* bsrc = reinterpret_cast<const char*>(g_bfrag)
                           + (size_t)rank * 65536;
        #pragma unroll
        for (int i = 0; i < 16; i++) {
            uint32_t o = (uint32_t)(i * 4096 + tid * 16);
            CP_ASYNC16(sb + SM_B + o, bsrc + o);
        }
        asm volatile("cp.async.commit_group;" ::: "memory");
    }

    const int r = tid >> 2;   // A row owned on the load path
    const int q = tid & 3;    // 32-float quarter

    // stage: load 64x128 f32 rows, norms, cvt f16 -> A[buf]
    auto stage = [&](int t_, int buf) {
        const float4* src = reinterpret_cast<const float4*>(
            X + ((size_t)t_ * BM + r) * DDIM + q * 32);
        float ss = 0.f;
        uint2 u[8];
        #pragma unroll
        for (int i = 0; i < 8; i++) {
            float4 v = src[i];
            ss += v.x * v.x + v.y * v.y + v.z * v.z + v.w * v.w;
            __half2 h0 = __floats2half2_rn(v.x, v.y);
            __half2 h1 = __floats2half2_rn(v.z, v.w);
            u[i].x = *reinterpret_cast<uint32_t*>(&h0);
            u[i].y = *reinterpret_cast<uint32_t*>(&h1);
        }
        ss += __shfl_xor_sync(0xffffffffu, ss, 1);
        ss += __shfl_xor_sync(0xffffffffu, ss, 2);
        if (q == 0)
            reinterpret_cast<float*>(smem + SM_NRM)[buf * 64 + r] =
                1.0f / fmaxf(sqrtf(ss), 1e-8f);
        char* adst = smem + (buf ? SM_A1 : SM_A0) + r * A_STRIDE + q * 64;
        #pragma unroll
        for (int i = 0; i < 8; i++)
            *reinterpret_cast<uint2*>(adst + i * 8) = u[i];
    };

    stage(cid, 0);
    asm volatile("cp.async.wait_group 0;" ::: "memory");
    __syncthreads();

    const uint2* Bs = reinterpret_cast<const uint2*>(smem + SM_B);
    float* rs_arr   = reinterpret_cast<float*>(smem + SM_RS);
    float* inv_arr  = reinterpret_cast<float*>(smem + SM_INV);
    float* peer_ps  = reinterpret_cast<float*>(smem + SM_PEER);

    int p = 0;
    for (int tile = cid; tile < tiles; tile += nclusters) {
        const int tnext = tile + nclusters;
        const bool hn = tnext < tiles;

        // ---- mma phase: warp = 64 rows x 32 cols ----
        float acc[4][4][4];
        #pragma unroll
        for (int sl = 0; sl < 4; sl++)
            #pragma unroll
            for (int t = 0; t < 4; t++)
                #pragma unroll
                for (int c = 0; c < 4; c++) acc[sl][t][c] = 0.f;

        const uint32_t abase = sb + (p ? SM_A1 : SM_A0);
        #pragma unroll
        for (int s = 0; s < 8; s++) {
            uint32_t a[4][4];
            #pragma unroll
            for (int sl = 0; sl < 4; sl++) {
                uint32_t addr = abase + (uint32_t)((sl * 16 + lrow) * A_STRIDE
                                                   + s * 32 + lkoff);
                asm volatile(
                    "ldmatrix.sync.aligned.m8n8.x4.shared.b16 {%0,%1,%2,%3},[%4];"
                    : "=r"(a[sl][0]), "=r"(a[sl][1]),
                      "=r"(a[sl][2]), "=r"(a[sl][3])
                    : "r"(addr));
            }
            #pragma unroll
            for (int t = 0; t < 4; t++) {
                uint2 b = Bs[(s * 32 + wid * 4 + t) * 32 + lane];
                #pragma unroll
                for (int sl = 0; sl < 4; sl++)
                    mma_f16(acc[sl][t], a[sl], b.x, b.y);
            }
        }

        // ---- pass 1: exp + per-warp partial row sums ----
        const float* nrmc = reinterpret_cast<const float*>(smem + SM_NRM) + p * 64;
        #pragma unroll
        for (int sl = 0; sl < 4; sl++) {
            #pragma unroll
            for (int h = 0; h < 2; h++) {
                const int row = sl * 16 + h * 8 + g;
                const float nv = nrmc[row];
                float psum = 0.f;
                #pragma unroll
                for (int t = 0; t < 4; t++) {
                    float e0 = __expf(acc[sl][t][h * 2 + 0] * nv - 1.0f);
                    float e1 = __expf(acc[sl][t][h * 2 + 1] * nv - 1.0f);
                    acc[sl][t][h * 2 + 0] = e0;
                    acc[sl][t][h * 2 + 1] = e1;
                    psum += e0 + e1;
                }
                psum += __shfl_xor_sync(0xffffffffu, psum, 1);
                psum += __shfl_xor_sync(0xffffffffu, psum, 2);
                if (kq == 0) rs_arr[wid * 64 + row] = psum;
            }
        }
        __syncthreads();

        // ---- exchange partial sums with peer CTA ----
        float s8 = 0.f;
        if (tid < 64) {
            #pragma unroll
            for (int w = 0; w < 8; w++) s8 += rs_arr[w * 64 + tid];
            uint32_t laddr = sb + SM_PEER + (uint32_t)(p * 64 + tid) * 4;
            uint32_t raddr;
            asm("mapa.shared::cluster.u32 %0, %1, %2;"
                : "=r"(raddr) : "r"(laddr), "r"(rank ^ 1u));
            asm volatile("st.shared::cluster.f32 [%0], %1;"
                         :: "r"(raddr), "f"(s8) : "memory");
        }
        asm volatile("barrier.cluster.arrive.aligned;" ::: "memory");

        // ---- stage next A while the barrier settles ----
        if (hn) stage(tnext, p ^ 1);

        asm volatile("barrier.cluster.wait.aligned;" ::: "memory");

        if (tid < 64)
            inv_arr[tid] = 1.0f / (s8 + peer_ps[p * 64 + tid]);
        __syncthreads();

        // ---- pass 2: scale + store this CTA's 256-class half ----
        #pragma unroll
        for (int sl = 0; sl < 4; sl++) {
            #pragma unroll
            for (int h = 0; h < 2; h++) {
                const int row = sl * 16 + h * 8 + g;
                const float iv = inv_arr[row];
                float* op = out + ((size_t)tile * BM + row) * KCLS
                                + rank * 256 + wid * 32 + kq * 2;
                #pragma unroll
                for (int t = 0; t < 4; t++) {
                    float2 v = make_float2(acc[sl][t][h * 2 + 0] * iv,
                                           acc[sl][t][h * 2 + 1] * iv);
                    *reinterpret_cast<float2*>(op + t * 8) = v;
                }
            }
        }

        p ^= 1;
    }
}

// ---------------- launch ----------------

extern "C" void kernel_launch(void* const* d_in, const int* in_sizes, int n_in,
                              void* d_out, int out_size) {
    const float* X   = (const float*)d_in[0];   // [N,128]
    const float* muK = (const float*)d_in[1];   // [512,128]
    float* out = (float*)d_out;                 // [N,512]

    static int sms = 0;
    if (!sms) {
        cudaDeviceGetAttribute(&sms, cudaDevAttrMultiProcessorCount, 0);
        if (sms <= 0) sms = 148;
        cudaFuncSetAttribute(ncm_main,
                             cudaFuncAttributeMaxDynamicSharedMemorySize,
                             SM_TOTAL);
    }

    int N = in_sizes[0] / DDIM;
    int tiles = N / BM;                          // 4096
    int nclusters = sms < tiles ? sms : tiles;   // 1 cluster (2 CTAs) per SM pair slot

    ncm_prep<<<KCLS, DDIM>>>(muK);
    ncm_main<<<2 * nclusters, 256, SM_TOTAL>>>(X, out, tiles, nclusters);
}

// round 5
// speedup vs baseline: 1.5865x; 1.5865x over previous
#include <cuda_runtime.h>
#include <cuda_fp16.h>
#include <cstdint>

// ============================================================================
// NCMOpenMax: probas = softmax(cos(X, muK), axis=1)
//   X [262144,128] f32, muK [512,128] f32, out [262144,512] f32
//
// fp16 mma.sync.m16n8k16, persistent CTAs (1/SM, 256 thr).
// B (normalized muK, fp16 fragments) lives ENTIRELY IN REGISTERS: each warp
// owns 64 classes -> 128 B-regs/thread, loaded once. No B smem, no B LDS.
// Tile = 32 rows x 512 classes. A double-buffered in smem (LDG f32 -> cvt f16
// -> STS -> ldmatrix). Prep kernel permutes class columns so the epilogue
// writes with STG.128. cos<=1 => fixed shift exp2(s*c1 - log2e): exact
// softmax, no max pass.
// ============================================================================

static constexpr int DDIM = 128;
static constexpr int KCLS = 512;
static constexpr int BM   = 32;

// B fragments fp16: [s(8)][t(64)][lane(32)] x uint2 (4 halves)
__device__ __half g_bfrag[8 * 64 * 32 * 4];   // 128 KB

// ---- smem layout (bytes) ----
static constexpr int A_STRIDE = 272;              // 128 halves + 16B pad
static constexpr int A_BYTES  = BM * A_STRIDE;    // 8704
static constexpr int SM_A0    = 0;
static constexpr int SM_A1    = A_BYTES;          // 8704
static constexpr int SM_NRM   = 2 * A_BYTES;      // 17408 (2 x 32 f32)
static constexpr int SM_RS    = SM_NRM + 256;     // 17664 (8 x 32 f32)
static constexpr int SM_TOTAL = SM_RS + 1024;     // 18688

__device__ __forceinline__ uint32_t smem_u32(const void* p) {
    uint32_t a;
    asm("{ .reg .u64 t; cvta.to.shared.u64 t, %1; cvt.u32.u64 %0, t; }"
        : "=r"(a) : "l"(p));
    return a;
}

__device__ __forceinline__ void mma_f16(float* d, const uint32_t* a,
                                        uint32_t b0, uint32_t b1) {
    asm volatile(
        "mma.sync.aligned.m16n8k16.row.col.f32.f16.f16.f32 "
        "{%0,%1,%2,%3},{%4,%5,%6,%7},{%8,%9},{%0,%1,%2,%3};"
        : "+f"(d[0]), "+f"(d[1]), "+f"(d[2]), "+f"(d[3])
        : "r"(a[0]), "r"(a[1]), "r"(a[2]), "r"(a[3]), "r"(b0), "r"(b1));
}

__device__ __forceinline__ float ex2f(float x) {
    float r;
    asm("ex2.approx.ftz.f32 %0, %1;" : "=f"(r) : "f"(x));
    return r;
}

// ---------------- prep: normalize muK -> permuted fp16 fragments -----------

__global__ void ncm_prep(const float* __restrict__ muK) {
    __shared__ float pp[4];
    int n = blockIdx.x;       // class (output column)
    int k = threadIdx.x;      // feature
    float v = muK[n * DDIM + k];
    float ss = v * v;
    #pragma unroll
    for (int o = 16; o > 0; o >>= 1)
        ss += __shfl_xor_sync(0xffffffffu, ss, o);
    if ((k & 31) == 0) pp[k >> 5] = ss;
    __syncthreads();
    float inv = 1.0f / fmaxf(sqrtf(pp[0] + pp[1] + pp[2] + pp[3]), 1e-8f);

    // column permutation: output col n -> fragment position F such that a
    // thread's 4 values per tile-pair are contiguous output columns.
    // n = wb*64 + u*16 + kq*4 + hi*2 + e  ->  F = wb*64 + u*16 + hi*8 + kq*2 + e
    int wb = n >> 6, nl = n & 63;
    int u  = nl >> 4, j = nl & 15;
    int kq = j >> 2, hi = (j >> 1) & 1, e = j & 1;
    int F  = wb * 64 + u * 16 + hi * 8 + kq * 2 + e;
    int t  = F >> 3;                 // 8-class fragment tile
    int fc = F & 7;                  // column within tile

    // m16n8k16 .col B fragment: lane = fc*4 + ((k%16 & 7)>>1)
    int s    = k >> 4;
    int kk   = k & 15;
    int lane = fc * 4 + ((kk & 7) >> 1);
    int idx  = ((kk >= 8) ? 2 : 0) + (kk & 1);
    g_bfrag[(((s * 64 + t) * 32 + lane) << 2) + idx] = __float2half_rn(v * inv);
}

// ---------------- main: persistent GEMM + fused softmax ----------------

__global__ void __launch_bounds__(256, 1)
ncm_main(const float* __restrict__ X, float* __restrict__ out,
         int tiles, int nct) {
    extern __shared__ char smem[];
    const uint32_t sb = smem_u32(smem);
    const int tid  = threadIdx.x;
    const int lane = tid & 31;
    const int wid  = tid >> 5;
    const int g    = lane >> 2;
    const int kq   = lane & 3;

    // ldmatrix lane addressing (x4: two 16-row slabs x two 8-col k-halves)
    const int m_    = lane >> 3;
    const int lrow  = ((m_ & 1) << 3) + (lane & 7);
    const int lkoff = (m_ >> 1) << 4;

    float* nrm_arr = reinterpret_cast<float*>(smem + SM_NRM);
    float* rs_arr  = reinterpret_cast<float*>(smem + SM_RS);

    // ---- B into registers: warp wid owns classes [wid*64, wid*64+64) ----
    uint2 breg[8][8];
    {
        const uint2* bsrc = reinterpret_cast<const uint2*>(g_bfrag);
        #pragma unroll
        for (int s = 0; s < 8; s++)
            #pragma unroll
            for (int t = 0; t < 8; t++)
                breg[s][t] = bsrc[(s * 64 + wid * 8 + t) * 32 + lane];
    }

    const int r = tid >> 3;   // A row owned on load path (32 rows, 8 thr/row)
    const int q = tid & 7;    // float4 phase within row
    constexpr float LOG2E = 1.4426950408889634f;

    // stage: given x[4] (float4 f32), write inv-norm*log2e and f16 A tile
    auto stage = [&](const float4* x, int buf) {
        float ss = 0.f;
        #pragma unroll
        for (int i = 0; i < 4; i++)
            ss += x[i].x * x[i].x + x[i].y * x[i].y +
                  x[i].z * x[i].z + x[i].w * x[i].w;
        ss += __shfl_xor_sync(0xffffffffu, ss, 1);
        ss += __shfl_xor_sync(0xffffffffu, ss, 2);
        ss += __shfl_xor_sync(0xffffffffu, ss, 4);
        if (q == 0)
            nrm_arr[buf * 32 + r] = LOG2E / fmaxf(sqrtf(ss), 1e-8f);
        char* adst = smem + (buf ? SM_A1 : SM_A0) + r * A_STRIDE;
        #pragma unroll
        for (int i = 0; i < 4; i++) {
            __half2 h0 = __floats2half2_rn(x[i].x, x[i].y);
            __half2 h1 = __floats2half2_rn(x[i].z, x[i].w);
            uint2 u2;
            u2.x = *reinterpret_cast<uint32_t*>(&h0);
            u2.y = *reinterpret_cast<uint32_t*>(&h1);
            *reinterpret_cast<uint2*>(adst + (q + 8 * i) * 8) = u2;
        }
    };

    // ---- preamble: stage tile0 ----
    {
        const float4* src = reinterpret_cast<const float4*>(X)
                            + ((size_t)blockIdx.x * BM + r) * 32;
        float4 x[4];
        #pragma unroll
        for (int i = 0; i < 4; i++) x[i] = src[q + 8 * i];
        stage(x, 0);
    }
    __syncthreads();

    int p = 0;
    for (int tile = blockIdx.x; tile < tiles; tile += nct) {
        const bool hn = (tile + nct) < tiles;

        // ---- mma phase: 32 rows x 512 cols, B from regs ----
        float acc[2][8][4];
        #pragma unroll
        for (int sl = 0; sl < 2; sl++)
            #pragma unroll
            for (int t = 0; t < 8; t++)
                #pragma unroll
                for (int c = 0; c < 4; c++) acc[sl][t][c] = 0.f;

        const uint32_t abase = sb + (p ? SM_A1 : SM_A0);
        #pragma unroll
        for (int s = 0; s < 8; s++) {
            uint32_t a0[4], a1[4];
            uint32_t ad0 = abase + (uint32_t)(lrow * A_STRIDE + s * 32 + lkoff);
            asm volatile(
                "ldmatrix.sync.aligned.m8n8.x4.shared.b16 {%0,%1,%2,%3},[%4];"
                : "=r"(a0[0]), "=r"(a0[1]), "=r"(a0[2]), "=r"(a0[3])
                : "r"(ad0));
            asm volatile(
                "ldmatrix.sync.aligned.m8n8.x4.shared.b16 {%0,%1,%2,%3},[%4];"
                : "=r"(a1[0]), "=r"(a1[1]), "=r"(a1[2]), "=r"(a1[3])
                : "r"(ad0 + 16 * A_STRIDE));
            #pragma unroll
            for (int t = 0; t < 8; t++) {
                mma_f16(acc[0][t], a0, breg[s][t].x, breg[s][t].y);
                mma_f16(acc[1][t], a1, breg[s][t].x, breg[s][t].y);
            }
        }

        // ---- issue next-tile A loads (latency hidden under exp pass) ----
        float4 x[4];
        if (hn) {
            const float4* src = reinterpret_cast<const float4*>(X)
                                + ((size_t)(tile + nct) * BM + r) * 32;
            #pragma unroll
            for (int i = 0; i < 4; i++) x[i] = src[q + 8 * i];
        }

        // ---- pass 1: e = exp2(acc*c1 - log2e), partial row sums ----
        const float* nrmc = nrm_arr + p * 32;
        #pragma unroll
        for (int sl = 0; sl < 2; sl++) {
            #pragma unroll
            for (int h = 0; h < 2; h++) {
                const int row = sl * 16 + h * 8 + g;
                const float c1 = nrmc[row];
                float psum = 0.f;
                #pragma unroll
                for (int t = 0; t < 8; t++) {
                    float e0 = ex2f(fmaf(acc[sl][t][h * 2 + 0], c1, -LOG2E));
                    float e1 = ex2f(fmaf(acc[sl][t][h * 2 + 1], c1, -LOG2E));
                    acc[sl][t][h * 2 + 0] = e0;
                    acc[sl][t][h * 2 + 1] = e1;
                    psum += e0 + e1;
                }
                psum += __shfl_xor_sync(0xffffffffu, psum, 1);
                psum += __shfl_xor_sync(0xffffffffu, psum, 2);
                if (kq == 0) rs_arr[wid * 32 + row] = psum;
            }
        }
        __syncthreads();

        // ---- pass 2: per-thread denominators, scale, STG.128 ----
        #pragma unroll
        for (int sl = 0; sl < 2; sl++) {
            #pragma unroll
            for (int h = 0; h < 2; h++) {
                const int row = sl * 16 + h * 8 + g;
                float den = 0.f;
                #pragma unroll
                for (int w = 0; w < 8; w++) den += rs_arr[w * 32 + row];
                const float iv = 1.0f / den;
                float* op = out + ((size_t)tile * BM + row) * KCLS
                                + wid * 64 + kq * 4;
                #pragma unroll
                for (int u = 0; u < 4; u++) {
                    float4 v;
                    v.x = acc[sl][2 * u + 0][h * 2 + 0] * iv;
                    v.y = acc[sl][2 * u + 0][h * 2 + 1] * iv;
                    v.z = acc[sl][2 * u + 1][h * 2 + 0] * iv;
                    v.w = acc[sl][2 * u + 1][h * 2 + 1] * iv;
                    *reinterpret_cast<float4*>(op + u * 16) = v;
                }
            }
        }

        // ---- stage next A ----
        if (hn) stage(x, p ^ 1);
        p ^= 1;
        __syncthreads();
    }
}

// ---------------- launch ----------------

extern "C" void kernel_launch(void* const* d_in, const int* in_sizes, int n_in,
                              void* d_out, int out_size) {
    const float* X   = (const float*)d_in[0];   // [N,128]
    const float* muK = (const float*)d_in[1];   // [512,128]
    float* out = (float*)d_out;                 // [N,512]

    static int sms = 0;
    if (!sms) {
        cudaDeviceGetAttribute(&sms, cudaDevAttrMultiProcessorCount, 0);
        if (sms <= 0) sms = 148;
        cudaFuncSetAttribute(ncm_main,
                             cudaFuncAttributeMaxDynamicSharedMemorySize,
                             SM_TOTAL);
    }

    int N = in_sizes[0] / DDIM;
    int tiles = N / BM;                  // 8192
    int nct = sms < tiles ? sms : tiles;

    ncm_prep<<<KCLS, DDIM>>>(muK);
    ncm_main<<<nct, 256, SM_TOTAL>>>(X, out, tiles, nct);
}